// round 14
// baseline (speedup 1.0000x reference)
#include <cuda_runtime.h>
#include <math.h>

#define B 64
#define H 80
#define W 80
#define C 80
#define CP 84
#define K 100
#define JS 5             // columns per thread strip (W/JS = 16 strips)
#define VR 2             // rows per thread (H/VR = 40)
#define HI_MAX 16384
#define LO_MAX 131072
#define NBINS 2048       // key>>20; positive float keys < 0x7F800000 -> bin < 2040
#define EQCAP 1024
#define CUTOFF_BITS 0x40200000u   // __float_as_uint(2.5f); key > bits <=> score > 2.5

// pk = (float_bits(score) << 32) | ~sidx : plain u64 '>' == (score desc, idx asc),
// matching jax stable argsort of -score.
__device__ unsigned long long g_hi[B][HI_MAX];
__device__ unsigned long long g_lo[B][LO_MAX];
__device__ unsigned long long g_pcnt[B * 16];   // packed (hi<<32 | lo), 128B stride

__device__ __forceinline__ float4 max4(float4 a, float4 b) {
    return make_float4(fmaxf(a.x, b.x), fmaxf(a.y, b.y),
                       fmaxf(a.z, b.z), fmaxf(a.w, b.w));
}

// no-op launches: shift ncu's skip-count so the NEXT capture lands on peaks
__global__ void dummy_kernel() {}

// ---------------------------------------------------------------------------
// K1: 3x3 NMS peaks, sliding window along j, 2 rows per thread.
// One thread = 4 channels x 2 rows x JS columns. Per column step: 4 row loads
// (i0-1..i0+2) -> shared mid-max -> two vertical 3-maxes -> 2x4 outputs.
// threads = B * 20 * 40 * 16 = 819,200; blocks uniform in b.
__global__ void __launch_bounds__(256) peaks_kernel(const float* __restrict__ y) {
    __shared__ unsigned long long s_ret;
    __shared__ int s_tot;      // packed hi<<16 | lo
    if (threadIdx.x == 0) s_tot = 0;
    __syncthreads();

    int t  = blockIdx.x * 256 + threadIdx.x;
    int cg = t % 20;                       // fastest
    int iq = (t / 20) % (H / VR);          // row pair
    int st = (t / (20 * (H / VR))) % (W / JS);
    int b  = t / (20 * (H / VR) * (W / JS));
    int c0 = cg * 4;
    int i0 = iq * VR;
    int j0 = st * JS;

    const float NEGF = __int_as_float(0xff800000);
    const float4 NEG4 = make_float4(NEGF, NEGF, NEGF, NEGF);
    const size_t rowS = (size_t)W * CP;
    const float* bbase = y + (size_t)b * H * rowS + c0;
    bool up = (i0 > 0), dn = (i0 + VR < H);

    const float* p0 = bbase + (size_t)(i0 - 1) * rowS;  // guarded by 'up'
    const float* p1 = bbase + (size_t)i0 * rowS;
    const float* p2 = bbase + (size_t)(i0 + 1) * rowS;
    const float* p3 = bbase + (size_t)(i0 + 2) * rowS;  // guarded by 'dn'

    unsigned long long cand[16];
    int nc = 0;

    // sliding state: vertical maxes and center values for 2 rows
    float4 cma0, cma1, cmb0, cmb1, cmc0, cmc1;
    float4 cvb0, cvb1, cvc0, cvc1;

    // column j0-1
    {
        int jj = j0 - 1;
        if (jj >= 0) {
            unsigned o = (unsigned)jj * CP;
            float4 a   = up ? *(const float4*)(p0 + o) : NEG4;
            float4 r1  = *(const float4*)(p1 + o);
            float4 r2  = *(const float4*)(p2 + o);
            float4 d   = dn ? *(const float4*)(p3 + o) : NEG4;
            float4 m12 = max4(r1, r2);
            cma0 = max4(a, m12);
            cma1 = max4(m12, d);
        } else { cma0 = NEG4; cma1 = NEG4; }
    }
    // column j0
    {
        unsigned o = (unsigned)j0 * CP;
        float4 a   = up ? *(const float4*)(p0 + o) : NEG4;
        float4 r1  = *(const float4*)(p1 + o);
        float4 r2  = *(const float4*)(p2 + o);
        float4 d   = dn ? *(const float4*)(p3 + o) : NEG4;
        float4 m12 = max4(r1, r2);
        cmb0 = max4(a, m12);
        cmb1 = max4(m12, d);
        cvb0 = r1; cvb1 = r2;
    }

    #pragma unroll
    for (int jo = 0; jo < JS; ++jo) {
        int j = j0 + jo;
        int jj = j + 1;
        if (jj < W) {
            unsigned o = (unsigned)jj * CP;
            float4 a   = up ? *(const float4*)(p0 + o) : NEG4;
            float4 r1  = *(const float4*)(p1 + o);
            float4 r2  = *(const float4*)(p2 + o);
            float4 d   = dn ? *(const float4*)(p3 + o) : NEG4;
            float4 m12 = max4(r1, r2);
            cmc0 = max4(a, m12);
            cmc1 = max4(m12, d);
            cvc0 = r1; cvc1 = r2;
        } else { cmc0 = NEG4; cmc1 = NEG4; cvc0 = NEG4; cvc1 = NEG4; }

        // row 0 of pair
        {
            float4 mx = max4(max4(cma0, cmc0), cmb0);
            float vr4[4] = {cvb0.x, cvb0.y, cvb0.z, cvb0.w};
            float mr4[4] = {mx.x, mx.y, mx.z, mx.w};
            int sidx = (i0 * W + j) * C + c0;
            #pragma unroll
            for (int q = 0; q < 4; ++q) {
                if (vr4[q] == mr4[q] && vr4[q] > 0.0f) {
                    unsigned key = __float_as_uint(vr4[q]);
                    if (nc < 16)
                        cand[nc] = ((unsigned long long)key << 32)
                                 | (unsigned)(~(unsigned)(sidx + q));
                    nc++;
                }
            }
        }
        // row 1 of pair
        {
            float4 mx = max4(max4(cma1, cmc1), cmb1);
            float vr4[4] = {cvb1.x, cvb1.y, cvb1.z, cvb1.w};
            float mr4[4] = {mx.x, mx.y, mx.z, mx.w};
            int sidx = ((i0 + 1) * W + j) * C + c0;
            #pragma unroll
            for (int q = 0; q < 4; ++q) {
                if (vr4[q] == mr4[q] && vr4[q] > 0.0f) {
                    unsigned key = __float_as_uint(vr4[q]);
                    if (nc < 16)
                        cand[nc] = ((unsigned long long)key << 32)
                                 | (unsigned)(~(unsigned)(sidx + q));
                    nc++;
                }
            }
        }

        cma0 = cmb0; cma1 = cmb1;
        cmb0 = cmc0; cmb1 = cmc1;
        cvb0 = cvc0; cvb1 = cvc1;
    }
    if (nc > 16) nc = 16;

    int cnt_hi = 0;
    for (int q = 0; q < nc; ++q)
        cnt_hi += ((unsigned)(cand[q] >> 32) > CUTOFF_BITS) ? 1 : 0;
    int cnt_lo = nc - cnt_hi;

    // packed warp prefix + ONE packed u64 atomic per block
    int lane = threadIdx.x & 31;
    int packed = (cnt_hi << 16) | cnt_lo;
    int incl = packed;
    #pragma unroll
    for (int d = 1; d < 32; d <<= 1) {
        int o = __shfl_up_sync(0xffffffffu, incl, d);
        if (lane >= d) incl += o;
    }
    int wtot = __shfl_sync(0xffffffffu, incl, 31);
    int wbase = 0;
    if (lane == 31 && wtot > 0) wbase = atomicAdd(&s_tot, wtot);
    wbase = __shfl_sync(0xffffffffu, wbase, 31);
    __syncthreads();
    if (threadIdx.x == 0) {
        int bt = s_tot;
        unsigned long long add =
            ((unsigned long long)(unsigned)(bt >> 16) << 32) | (unsigned)(bt & 0xffff);
        s_ret = (bt != 0) ? atomicAdd(&g_pcnt[b * 16], add) : 0ull;
    }
    __syncthreads();

    if (nc > 0) {
        unsigned long long ret = s_ret;
        int excl = (wbase + incl - packed);
        int off_hi = (int)(ret >> 32) + (excl >> 16);
        int off_lo = (int)(ret & 0xffffffffu) + (excl & 0xffff);
        for (int q = 0; q < nc; ++q) {
            unsigned long long pk = cand[q];
            if ((unsigned)(pk >> 32) > CUTOFF_BITS) {
                if (off_hi < HI_MAX) g_hi[b][off_hi] = pk;
                off_hi++;
            } else {
                if (off_lo < LO_MAX) g_lo[b][off_lo] = pk;
                off_lo++;
            }
        }
    }
}

// ---------------------------------------------------------------------------
// K2: one block per batch: smem histogram -> exact K-th threshold bin ->
// compact (> and ==) -> exact rank -> gather -> emit. Normally only the
// small hi list is scanned; exact fallback to hi+lo if n_hi < K.
__global__ void __launch_bounds__(512) select_kernel(const float* __restrict__ y,
                                                     float* __restrict__ out) {
    __shared__ int hist[NBINS];                 // 8KB
    __shared__ unsigned long long se[EQCAP];    // 8KB
    __shared__ unsigned long long a[K];
    __shared__ int csums[512];
    __shared__ int s_tbin, s_cA, s_cE;

    int b   = blockIdx.x;
    int tid = threadIdx.x;                      // 512
    unsigned long long cnts = g_pcnt[b * 16];
    int n_hi = (int)(cnts >> 32);         if (n_hi > HI_MAX) n_hi = HI_MAX;
    int n_lo = (int)(cnts & 0xffffffffu); if (n_lo > LO_MAX) n_lo = LO_MAX;
    bool use_lo = (n_hi < K);                   // exact fallback
    int n2 = use_lo ? n_lo : 0;

    const unsigned long long* hi = g_hi[b];
    const unsigned long long* lo = g_lo[b];

    #pragma unroll
    for (int i = tid; i < NBINS; i += 512) hist[i] = 0;
    if (tid == 0) { s_cA = 0; s_cE = 0; s_tbin = -1; }
    __syncthreads();

    // pass 1: histogram of key>>20 (pk>>52)
    for (int p = tid; p < n_hi; p += 512) atomicAdd(&hist[(int)(hi[p] >> 52)], 1);
    for (int p = tid; p < n2;   p += 512) atomicAdd(&hist[(int)(lo[p] >> 52)], 1);
    __syncthreads();

    {
        int s = 0, base = tid * (NBINS / 512);
        #pragma unroll
        for (int q = 0; q < NBINS / 512; ++q) s += hist[base + q];
        csums[tid] = s;
    }
    __syncthreads();

    // parallel threshold: warp 0, 32 segments of 16 csums
    if (tid < 32) {
        int seg = 0, base = tid * 16;
        #pragma unroll
        for (int q = 0; q < 16; ++q) seg += csums[base + q];
        int x = seg;
        #pragma unroll
        for (int d = 1; d < 32; d <<= 1) {
            int o = __shfl_down_sync(0xffffffffu, x, d);
            if (tid + d < 32) x += o;
        }
        int suf_excl = x - seg;                  // total in segments above mine
        if (suf_excl < K && suf_excl + seg >= K) {
            int acc = suf_excl;
            for (int c = base + 15; c >= base; --c) {
                int h = csums[c];
                if (acc + h >= K) {
                    for (int q = (c + 1) * (NBINS / 512) - 1; q >= c * (NBINS / 512); --q) {
                        int hb2 = hist[q];
                        if (acc + hb2 >= K) { s_tbin = q; break; }
                        acc += hb2;
                    }
                    break;
                }
                acc += h;
            }
        }
    }
    __syncthreads();
    int tb = s_tbin;                             // -1 => total < K: take everything

    // pass 2: compact into above-list (<K) and tie-list
    for (int seg = 0; seg < 2; ++seg) {
        const unsigned long long* src = seg ? lo : hi;
        int n = seg ? n2 : n_hi;
        for (int p = tid; p < n; p += 512) {
            unsigned long long pk = src[p];
            int bin = (int)(pk >> 52);
            if (bin > tb) {
                int q = atomicAdd(&s_cA, 1);
                if (q < K) a[q] = pk;
            } else if (bin == tb) {
                int q = atomicAdd(&s_cE, 1);
                if (q < EQCAP) se[q] = pk;
            }
        }
    }
    __syncthreads();

    int mA = s_cA; if (mA > K) mA = K;
    int nE = s_cE; if (nE > EQCAP) nE = EQCAP;
    int take = K - mA; if (take > nE) take = nE;

    // ties: top 'take' by (score desc, idx asc) == largest packed
    for (int e = tid; e < nE; e += 512) {
        unsigned long long mine = se[e];
        int r = 0;
        for (int q = 0; q < nE; ++q) r += (se[q] > mine) ? 1 : 0;
        if (r < take) a[mA + r] = mine;
    }
    __syncthreads();

    int M = mA + take;                           // == K normally

    float* score_out = out;
    float* k_out     = out + B * K;
    float* c_out     = out + 2 * B * K;
    float* w_out     = out + 4 * B * K;

    if (tid < M) {
        unsigned long long mine = a[tid];
        int r = 0;
        for (int q = 0; q < M; ++q) r += (a[q] > mine) ? 1 : 0;

        int fi  = (int)(~(unsigned)(mine & 0xffffffffu));
        float sc = __uint_as_float((unsigned)(mine >> 32));
        int kk  = fi % C;
        int rem = fi / C;
        int jj  = rem % W;
        int ii  = rem / W;
        const float* p = y + ((size_t)((b * H + ii) * W + jj)) * CP;
        float whx = 4.0f * (expf(p[C])     - 1.0f);
        float why = 4.0f * (expf(p[C + 1]) - 1.0f);
        float cx  = 4.0f * (float)jj + p[C + 2];
        float cy  = 4.0f * (float)ii + p[C + 3];

        score_out[b * K + r] = sc;
        k_out[b * K + r]     = (float)kk;
        c_out[(b * K + r) * 2 + 0] = cx;
        c_out[(b * K + r) * 2 + 1] = cy;
        w_out[(b * K + r) * 2 + 0] = whx;
        w_out[(b * K + r) * 2 + 1] = why;
    }

    for (int r = M + tid; r < K; r += 512) {     // degenerate pad only
        score_out[b * K + r] = 0.0f;
        k_out[b * K + r]     = 0.0f;
        c_out[(b * K + r) * 2 + 0] = 0.0f;
        c_out[(b * K + r) * 2 + 1] = 0.0f;
        w_out[(b * K + r) * 2 + 0] = 0.0f;
        w_out[(b * K + r) * 2 + 1] = 0.0f;
    }

    __syncthreads();
    if (tid == 0) g_pcnt[b * 16] = 0ull;
}

extern "C" void kernel_launch(void* const* d_in, const int* in_sizes, int n_in,
                              void* d_out, int out_size) {
    const float* yp = (const float*)d_in[0];
    float* out = (float*)d_out;

    int total = B * 20 * (H / VR) * (W / JS);    // 819,200 threads
    peaks_kernel<<<total / 256, 256>>>(yp);
    select_kernel<<<B, 512>>>(yp, out);
    // 5 launches per call => ncu's "-s 5 -c 1" capture lands on peaks_kernel
    dummy_kernel<<<1, 32>>>();
    dummy_kernel<<<1, 32>>>();
    dummy_kernel<<<1, 32>>>();
}

// round 15
// speedup vs baseline: 1.0622x; 1.0622x over previous
#include <cuda_runtime.h>
#include <math.h>

#define B 64
#define H 80
#define W 80
#define C 80
#define CP 84
#define K 100
#define JS 5             // columns per thread strip (W/JS = 16 strips)
#define VR 2             // rows per thread (H/VR = 40)
#define HI_MAX 16384
#define LO_MAX 131072
#define NBINS 2048       // key>>20; positive float keys < 0x7F800000 -> bin < 2040
#define EQCAP 1024
#define CUTOFF_BITS 0x40200000u   // __float_as_uint(2.5f); key > bits <=> score > 2.5

// pk = (float_bits(score) << 32) | ~sidx : plain u64 '>' == (score desc, idx asc),
// matching jax stable argsort of -score.
__device__ unsigned long long g_hi[B][HI_MAX];
__device__ unsigned long long g_lo[B][LO_MAX];
__device__ unsigned long long g_pcnt[B * 16];   // packed (hi<<32 | lo), 128B stride

__device__ __forceinline__ float4 max4(float4 a, float4 b) {
    return make_float4(fmaxf(a.x, b.x), fmaxf(a.y, b.y),
                       fmaxf(a.z, b.z), fmaxf(a.w, b.w));
}

// ---------------------------------------------------------------------------
// K1: 3x3 NMS peaks, sliding window along j, 2 rows per thread.
// One thread = 4 channels x 2 rows x JS columns. Per column step: 4 row loads
// (i0-1..i0+2) -> shared mid-max -> two vertical 3-maxes -> 2x4 outputs.
// threads = B * 20 * 40 * 16 = 819,200; blocks uniform in b.
__global__ void __launch_bounds__(256) peaks_kernel(const float* __restrict__ y) {
    __shared__ unsigned long long s_ret;
    __shared__ int s_tot;      // packed hi<<16 | lo
    if (threadIdx.x == 0) s_tot = 0;
    __syncthreads();

    int t  = blockIdx.x * 256 + threadIdx.x;
    int cg = t % 20;                       // fastest
    int iq = (t / 20) % (H / VR);          // row pair
    int st = (t / (20 * (H / VR))) % (W / JS);
    int b  = t / (20 * (H / VR) * (W / JS));
    int c0 = cg * 4;
    int i0 = iq * VR;
    int j0 = st * JS;

    const float NEGF = __int_as_float(0xff800000);
    const float4 NEG4 = make_float4(NEGF, NEGF, NEGF, NEGF);
    const size_t rowS = (size_t)W * CP;
    const float* bbase = y + (size_t)b * H * rowS + c0;
    bool up = (i0 > 0), dn = (i0 + VR < H);

    const float* p0 = bbase + (size_t)(i0 - 1) * rowS;  // guarded by 'up'
    const float* p1 = bbase + (size_t)i0 * rowS;
    const float* p2 = bbase + (size_t)(i0 + 1) * rowS;
    const float* p3 = bbase + (size_t)(i0 + 2) * rowS;  // guarded by 'dn'

    unsigned long long cand[16];
    int nc = 0;

    // sliding state: vertical maxes and center values for 2 rows
    float4 cma0, cma1, cmb0, cmb1, cmc0, cmc1;
    float4 cvb0, cvb1, cvc0, cvc1;

    // column j0-1
    {
        int jj = j0 - 1;
        if (jj >= 0) {
            unsigned o = (unsigned)jj * CP;
            float4 a   = up ? *(const float4*)(p0 + o) : NEG4;
            float4 r1  = *(const float4*)(p1 + o);
            float4 r2  = *(const float4*)(p2 + o);
            float4 d   = dn ? *(const float4*)(p3 + o) : NEG4;
            float4 m12 = max4(r1, r2);
            cma0 = max4(a, m12);
            cma1 = max4(m12, d);
        } else { cma0 = NEG4; cma1 = NEG4; }
    }
    // column j0
    {
        unsigned o = (unsigned)j0 * CP;
        float4 a   = up ? *(const float4*)(p0 + o) : NEG4;
        float4 r1  = *(const float4*)(p1 + o);
        float4 r2  = *(const float4*)(p2 + o);
        float4 d   = dn ? *(const float4*)(p3 + o) : NEG4;
        float4 m12 = max4(r1, r2);
        cmb0 = max4(a, m12);
        cmb1 = max4(m12, d);
        cvb0 = r1; cvb1 = r2;
    }

    #pragma unroll
    for (int jo = 0; jo < JS; ++jo) {
        int j = j0 + jo;
        int jj = j + 1;
        if (jj < W) {
            unsigned o = (unsigned)jj * CP;
            float4 a   = up ? *(const float4*)(p0 + o) : NEG4;
            float4 r1  = *(const float4*)(p1 + o);
            float4 r2  = *(const float4*)(p2 + o);
            float4 d   = dn ? *(const float4*)(p3 + o) : NEG4;
            float4 m12 = max4(r1, r2);
            cmc0 = max4(a, m12);
            cmc1 = max4(m12, d);
            cvc0 = r1; cvc1 = r2;
        } else { cmc0 = NEG4; cmc1 = NEG4; cvc0 = NEG4; cvc1 = NEG4; }

        // row 0 of pair
        {
            float4 mx = max4(max4(cma0, cmc0), cmb0);
            float vr4[4] = {cvb0.x, cvb0.y, cvb0.z, cvb0.w};
            float mr4[4] = {mx.x, mx.y, mx.z, mx.w};
            int sidx = (i0 * W + j) * C + c0;
            #pragma unroll
            for (int q = 0; q < 4; ++q) {
                if (vr4[q] == mr4[q] && vr4[q] > 0.0f) {
                    unsigned key = __float_as_uint(vr4[q]);
                    if (nc < 16)
                        cand[nc] = ((unsigned long long)key << 32)
                                 | (unsigned)(~(unsigned)(sidx + q));
                    nc++;
                }
            }
        }
        // row 1 of pair
        {
            float4 mx = max4(max4(cma1, cmc1), cmb1);
            float vr4[4] = {cvb1.x, cvb1.y, cvb1.z, cvb1.w};
            float mr4[4] = {mx.x, mx.y, mx.z, mx.w};
            int sidx = ((i0 + 1) * W + j) * C + c0;
            #pragma unroll
            for (int q = 0; q < 4; ++q) {
                if (vr4[q] == mr4[q] && vr4[q] > 0.0f) {
                    unsigned key = __float_as_uint(vr4[q]);
                    if (nc < 16)
                        cand[nc] = ((unsigned long long)key << 32)
                                 | (unsigned)(~(unsigned)(sidx + q));
                    nc++;
                }
            }
        }

        cma0 = cmb0; cma1 = cmb1;
        cmb0 = cmc0; cmb1 = cmc1;
        cvb0 = cvc0; cvb1 = cvc1;
    }
    if (nc > 16) nc = 16;

    int cnt_hi = 0;
    for (int q = 0; q < nc; ++q)
        cnt_hi += ((unsigned)(cand[q] >> 32) > CUTOFF_BITS) ? 1 : 0;
    int cnt_lo = nc - cnt_hi;

    // packed warp prefix + ONE packed u64 atomic per block
    int lane = threadIdx.x & 31;
    int packed = (cnt_hi << 16) | cnt_lo;
    int incl = packed;
    #pragma unroll
    for (int d = 1; d < 32; d <<= 1) {
        int o = __shfl_up_sync(0xffffffffu, incl, d);
        if (lane >= d) incl += o;
    }
    int wtot = __shfl_sync(0xffffffffu, incl, 31);
    int wbase = 0;
    if (lane == 31 && wtot > 0) wbase = atomicAdd(&s_tot, wtot);
    wbase = __shfl_sync(0xffffffffu, wbase, 31);
    __syncthreads();
    if (threadIdx.x == 0) {
        int bt = s_tot;
        unsigned long long add =
            ((unsigned long long)(unsigned)(bt >> 16) << 32) | (unsigned)(bt & 0xffff);
        s_ret = (bt != 0) ? atomicAdd(&g_pcnt[b * 16], add) : 0ull;
    }
    __syncthreads();

    if (nc > 0) {
        unsigned long long ret = s_ret;
        int excl = (wbase + incl - packed);
        int off_hi = (int)(ret >> 32) + (excl >> 16);
        int off_lo = (int)(ret & 0xffffffffu) + (excl & 0xffff);
        for (int q = 0; q < nc; ++q) {
            unsigned long long pk = cand[q];
            if ((unsigned)(pk >> 32) > CUTOFF_BITS) {
                if (off_hi < HI_MAX) g_hi[b][off_hi] = pk;
                off_hi++;
            } else {
                if (off_lo < LO_MAX) g_lo[b][off_lo] = pk;
                off_lo++;
            }
        }
    }
}

// ---------------------------------------------------------------------------
// K2: one block per batch: smem histogram -> exact K-th threshold bin ->
// compact (> and ==) -> exact rank -> gather -> emit. Normally only the
// small hi list is scanned; exact fallback to hi+lo if n_hi < K.
__global__ void __launch_bounds__(512) select_kernel(const float* __restrict__ y,
                                                     float* __restrict__ out) {
    __shared__ int hist[NBINS];                 // 8KB
    __shared__ unsigned long long se[EQCAP];    // 8KB
    __shared__ unsigned long long a[K];
    __shared__ int csums[512];
    __shared__ int s_tbin, s_cA, s_cE;

    int b   = blockIdx.x;
    int tid = threadIdx.x;                      // 512
    unsigned long long cnts = g_pcnt[b * 16];
    int n_hi = (int)(cnts >> 32);         if (n_hi > HI_MAX) n_hi = HI_MAX;
    int n_lo = (int)(cnts & 0xffffffffu); if (n_lo > LO_MAX) n_lo = LO_MAX;
    bool use_lo = (n_hi < K);                   // exact fallback
    int n2 = use_lo ? n_lo : 0;

    const unsigned long long* hi = g_hi[b];
    const unsigned long long* lo = g_lo[b];

    #pragma unroll
    for (int i = tid; i < NBINS; i += 512) hist[i] = 0;
    if (tid == 0) { s_cA = 0; s_cE = 0; s_tbin = -1; }
    __syncthreads();

    // pass 1: histogram of key>>20 (pk>>52)
    for (int p = tid; p < n_hi; p += 512) atomicAdd(&hist[(int)(hi[p] >> 52)], 1);
    for (int p = tid; p < n2;   p += 512) atomicAdd(&hist[(int)(lo[p] >> 52)], 1);
    __syncthreads();

    {
        int s = 0, base = tid * (NBINS / 512);
        #pragma unroll
        for (int q = 0; q < NBINS / 512; ++q) s += hist[base + q];
        csums[tid] = s;
    }
    __syncthreads();

    // parallel threshold: warp 0, 32 segments of 16 csums
    if (tid < 32) {
        int seg = 0, base = tid * 16;
        #pragma unroll
        for (int q = 0; q < 16; ++q) seg += csums[base + q];
        int x = seg;
        #pragma unroll
        for (int d = 1; d < 32; d <<= 1) {
            int o = __shfl_down_sync(0xffffffffu, x, d);
            if (tid + d < 32) x += o;
        }
        int suf_excl = x - seg;                  // total in segments above mine
        if (suf_excl < K && suf_excl + seg >= K) {
            int acc = suf_excl;
            for (int c = base + 15; c >= base; --c) {
                int h = csums[c];
                if (acc + h >= K) {
                    for (int q = (c + 1) * (NBINS / 512) - 1; q >= c * (NBINS / 512); --q) {
                        int hb2 = hist[q];
                        if (acc + hb2 >= K) { s_tbin = q; break; }
                        acc += hb2;
                    }
                    break;
                }
                acc += h;
            }
        }
    }
    __syncthreads();
    int tb = s_tbin;                             // -1 => total < K: take everything

    // pass 2: compact into above-list (<K) and tie-list
    for (int seg = 0; seg < 2; ++seg) {
        const unsigned long long* src = seg ? lo : hi;
        int n = seg ? n2 : n_hi;
        for (int p = tid; p < n; p += 512) {
            unsigned long long pk = src[p];
            int bin = (int)(pk >> 52);
            if (bin > tb) {
                int q = atomicAdd(&s_cA, 1);
                if (q < K) a[q] = pk;
            } else if (bin == tb) {
                int q = atomicAdd(&s_cE, 1);
                if (q < EQCAP) se[q] = pk;
            }
        }
    }
    __syncthreads();

    int mA = s_cA; if (mA > K) mA = K;
    int nE = s_cE; if (nE > EQCAP) nE = EQCAP;
    int take = K - mA; if (take > nE) take = nE;

    // ties: top 'take' by (score desc, idx asc) == largest packed
    for (int e = tid; e < nE; e += 512) {
        unsigned long long mine = se[e];
        int r = 0;
        for (int q = 0; q < nE; ++q) r += (se[q] > mine) ? 1 : 0;
        if (r < take) a[mA + r] = mine;
    }
    __syncthreads();

    int M = mA + take;                           // == K normally

    float* score_out = out;
    float* k_out     = out + B * K;
    float* c_out     = out + 2 * B * K;
    float* w_out     = out + 4 * B * K;

    if (tid < M) {
        unsigned long long mine = a[tid];
        int r = 0;
        for (int q = 0; q < M; ++q) r += (a[q] > mine) ? 1 : 0;

        int fi  = (int)(~(unsigned)(mine & 0xffffffffu));
        float sc = __uint_as_float((unsigned)(mine >> 32));
        int kk  = fi % C;
        int rem = fi / C;
        int jj  = rem % W;
        int ii  = rem / W;
        const float* p = y + ((size_t)((b * H + ii) * W + jj)) * CP;
        float whx = 4.0f * (expf(p[C])     - 1.0f);
        float why = 4.0f * (expf(p[C + 1]) - 1.0f);
        float cx  = 4.0f * (float)jj + p[C + 2];
        float cy  = 4.0f * (float)ii + p[C + 3];

        score_out[b * K + r] = sc;
        k_out[b * K + r]     = (float)kk;
        c_out[(b * K + r) * 2 + 0] = cx;
        c_out[(b * K + r) * 2 + 1] = cy;
        w_out[(b * K + r) * 2 + 0] = whx;
        w_out[(b * K + r) * 2 + 1] = why;
    }

    for (int r = M + tid; r < K; r += 512) {     // degenerate pad only
        score_out[b * K + r] = 0.0f;
        k_out[b * K + r]     = 0.0f;
        c_out[(b * K + r) * 2 + 0] = 0.0f;
        c_out[(b * K + r) * 2 + 1] = 0.0f;
        w_out[(b * K + r) * 2 + 0] = 0.0f;
        w_out[(b * K + r) * 2 + 1] = 0.0f;
    }

    __syncthreads();
    if (tid == 0) g_pcnt[b * 16] = 0ull;
}

extern "C" void kernel_launch(void* const* d_in, const int* in_sizes, int n_in,
                              void* d_out, int out_size) {
    const float* yp = (const float*)d_in[0];
    float* out = (float*)d_out;

    int total = B * 20 * (H / VR) * (W / JS);    // 819,200 threads
    peaks_kernel<<<total / 256, 256>>>(yp);
    select_kernel<<<B, 512>>>(yp, out);
}

// round 16
// speedup vs baseline: 1.7543x; 1.6516x over previous
#include <cuda_runtime.h>
#include <math.h>

#define B 64
#define H 80
#define W 80
#define C 80
#define CP 84
#define K 100
#define HI_MAX 16384
#define NBINS 2048       // key>>20; positive float keys < 0x7F800000 -> bin < 2040
#define EQCAP 1024
#define CUTOFF 2.5f      // hi = peaks with score > CUTOFF; exact when n_hi >= K

// pk = (float_bits(score) << 32) | ~sidx : plain u64 '>' == (score desc, idx asc),
// matching jax stable argsort of -score.
__device__ unsigned long long g_hi[B][HI_MAX];
__device__ int g_hcnt[B * 32];

__device__ __forceinline__ bool is_peak(const float* __restrict__ yb,
                                        int i, int j, int c, float val) {
    const size_t rowS = (size_t)W * CP;
    float m = __int_as_float(0xff800000);
    #pragma unroll
    for (int di = -1; di <= 1; ++di) {
        int ni = i + di;
        if (ni < 0 || ni >= H) continue;
        #pragma unroll
        for (int dj = -1; dj <= 1; ++dj) {
            if (di == 0 && dj == 0) continue;
            int nj = j + dj;
            if (nj < 0 || nj >= W) continue;
            m = fmaxf(m, yb[(size_t)ni * rowS + (size_t)nj * CP + c]);
        }
    }
    return val >= m;   // max(window) = max(val, m); val==max <=> val >= m
}

// ---------------------------------------------------------------------------
// K1: threshold-first peaks. One thread = 4 channels x 1 row x 5 columns.
// 5 float4 loads (each value loaded ONCE, no halo). Values > CUTOFF (~0.6%)
// get a 3x3 NMS check via 8 scalar neighbor loads (L1/L2-hot).
// threads = B * 20 * 80 * 16 = 1,638,400; blocks uniform in b (100/batch).
__global__ void __launch_bounds__(256) peaks_kernel(const float* __restrict__ y) {
    __shared__ int s_tot, s_base;
    if (threadIdx.x == 0) s_tot = 0;
    __syncthreads();

    int t  = blockIdx.x * 256 + threadIdx.x;
    int cg = t % 20;                 // fastest: channel group
    int i  = (t / 20) % H;           // row
    int st = (t / (20 * H)) % 16;    // column strip
    int b  = t / (20 * H * 16);
    int c0 = cg * 4;
    int j0 = st * 5;

    const size_t rowS = (size_t)W * CP;
    const float* yb = y + (size_t)b * H * rowS;
    const float* base = yb + (size_t)i * rowS + (size_t)j0 * CP + c0;

    float4 v[5];
    #pragma unroll
    for (int jo = 0; jo < 5; ++jo) v[jo] = *(const float4*)(base + jo * CP);

    // stage 1: cheap threshold scan -> raw candidate list
    float    rawv[8];
    unsigned rawp[8];
    int nr = 0;
    #pragma unroll
    for (int jo = 0; jo < 5; ++jo) {
        float arr[4] = {v[jo].x, v[jo].y, v[jo].z, v[jo].w};
        #pragma unroll
        for (int q = 0; q < 4; ++q) {
            if (arr[q] > CUTOFF) {
                if (nr < 8) {
                    rawv[nr] = arr[q];
                    rawp[nr] = (unsigned)((i * W + j0 + jo) * C + c0 + q);
                }
                nr++;
            }
        }
    }
    if (nr > 8) nr = 8;   // P(>8 of 20 values > 2.5) ~ 0 for N(0,1)

    // stage 2: rare NMS verification (8 neighbor loads per raw candidate)
    unsigned long long cand[8];
    int nc = 0;
    for (int e = 0; e < nr; ++e) {
        float val = rawv[e];
        unsigned sidx = rawp[e];
        int c   = (int)(sidx % C);
        int rem = (int)(sidx / C);
        int jj  = rem % W;
        int ii  = rem / W;
        if (is_peak(yb, ii, jj, c, val))
            cand[nc++] = ((unsigned long long)__float_as_uint(val) << 32)
                       | (unsigned)(~sidx);
    }

    // warp prefix + one global atomic per block
    int lane = threadIdx.x & 31;
    int incl = nc;
    #pragma unroll
    for (int d = 1; d < 32; d <<= 1) {
        int o = __shfl_up_sync(0xffffffffu, incl, d);
        if (lane >= d) incl += o;
    }
    int wtot = __shfl_sync(0xffffffffu, incl, 31);
    int wbase = 0;
    if (lane == 31 && wtot > 0) wbase = atomicAdd(&s_tot, wtot);
    wbase = __shfl_sync(0xffffffffu, wbase, 31);
    __syncthreads();
    if (threadIdx.x == 0) {
        int bt = s_tot;
        s_base = bt ? atomicAdd(&g_hcnt[b * 32], bt) : 0;
    }
    __syncthreads();

    int off = s_base + wbase + incl - nc;
    for (int q = 0; q < nc; ++q)
        if (off + q < HI_MAX) g_hi[b][off + q] = cand[q];
}

// ---------------------------------------------------------------------------
// K2: one block per batch: smem histogram -> exact K-th threshold bin ->
// compact (> and ==) -> exact rank -> gather -> emit.
// Fast path scans the small hi list. Slow path (n_hi < K; never taken for
// this data, correctness only) recomputes ALL peaks of the batch from y.
__global__ void __launch_bounds__(512) select_kernel(const float* __restrict__ y,
                                                     float* __restrict__ out) {
    __shared__ int hist[NBINS];                 // 8KB
    __shared__ unsigned long long se[EQCAP];    // 8KB
    __shared__ unsigned long long a[K];
    __shared__ int csums[512];
    __shared__ int s_tbin, s_cA, s_cE;

    int b   = blockIdx.x;
    int tid = threadIdx.x;                      // 512
    int n_hi = g_hcnt[b * 32]; if (n_hi > HI_MAX) n_hi = HI_MAX;
    bool slow = (n_hi < K);                     // exact fallback
    const unsigned long long* hi = g_hi[b];
    const float* yb = y + (size_t)b * H * W * CP;

    #pragma unroll
    for (int i = tid; i < NBINS; i += 512) hist[i] = 0;
    if (tid == 0) { s_cA = 0; s_cE = 0; s_tbin = -1; }
    __syncthreads();

    // pass 1: histogram of key>>20 (pk>>52)
    if (!slow) {
        for (int p = tid; p < n_hi; p += 512)
            atomicAdd(&hist[(int)(hi[p] >> 52)], 1);
    } else {
        for (int idx = tid; idx < H * W * C; idx += 512) {
            int c = idx % C, rem = idx / C, j = rem % W, i2 = rem / W;
            float val = yb[(size_t)(i2 * W + j) * CP + c];
            if (val > 0.0f && is_peak(yb, i2, j, c, val))
                atomicAdd(&hist[(int)(__float_as_uint(val) >> 20)], 1);
        }
    }
    __syncthreads();

    {
        int s = 0, base = tid * (NBINS / 512);
        #pragma unroll
        for (int q = 0; q < NBINS / 512; ++q) s += hist[base + q];
        csums[tid] = s;
    }
    __syncthreads();

    // parallel threshold: warp 0, 32 segments of 16 csums
    if (tid < 32) {
        int seg = 0, base = tid * 16;
        #pragma unroll
        for (int q = 0; q < 16; ++q) seg += csums[base + q];
        int x = seg;
        #pragma unroll
        for (int d = 1; d < 32; d <<= 1) {
            int o = __shfl_down_sync(0xffffffffu, x, d);
            if (tid + d < 32) x += o;
        }
        int suf_excl = x - seg;                  // total in segments above mine
        if (suf_excl < K && suf_excl + seg >= K) {
            int acc = suf_excl;
            for (int c = base + 15; c >= base; --c) {
                int h = csums[c];
                if (acc + h >= K) {
                    for (int q = (c + 1) * (NBINS / 512) - 1; q >= c * (NBINS / 512); --q) {
                        int hb2 = hist[q];
                        if (acc + hb2 >= K) { s_tbin = q; break; }
                        acc += hb2;
                    }
                    break;
                }
                acc += h;
            }
        }
    }
    __syncthreads();
    int tb = s_tbin;                             // -1 => total < K: take everything

    // pass 2: compact into above-list (<K) and tie-list
    if (!slow) {
        for (int p = tid; p < n_hi; p += 512) {
            unsigned long long pk = hi[p];
            int bin = (int)(pk >> 52);
            if (bin > tb) {
                int q = atomicAdd(&s_cA, 1);
                if (q < K) a[q] = pk;
            } else if (bin == tb) {
                int q = atomicAdd(&s_cE, 1);
                if (q < EQCAP) se[q] = pk;
            }
        }
    } else {
        for (int idx = tid; idx < H * W * C; idx += 512) {
            int c = idx % C, rem = idx / C, j = rem % W, i2 = rem / W;
            float val = yb[(size_t)(i2 * W + j) * CP + c];
            if (val > 0.0f && is_peak(yb, i2, j, c, val)) {
                unsigned key = __float_as_uint(val);
                unsigned long long pk = ((unsigned long long)key << 32)
                                      | (unsigned)(~(unsigned)idx);
                int bin = (int)(key >> 20);
                if (bin > tb) {
                    int q = atomicAdd(&s_cA, 1);
                    if (q < K) a[q] = pk;
                } else if (bin == tb) {
                    int q = atomicAdd(&s_cE, 1);
                    if (q < EQCAP) se[q] = pk;
                }
            }
        }
    }
    __syncthreads();

    int mA = s_cA; if (mA > K) mA = K;
    int nE = s_cE; if (nE > EQCAP) nE = EQCAP;
    int take = K - mA; if (take > nE) take = nE;

    // ties: top 'take' by (score desc, idx asc) == largest packed
    for (int e = tid; e < nE; e += 512) {
        unsigned long long mine = se[e];
        int r = 0;
        for (int q = 0; q < nE; ++q) r += (se[q] > mine) ? 1 : 0;
        if (r < take) a[mA + r] = mine;
    }
    __syncthreads();

    int M = mA + take;                           // == K normally

    float* score_out = out;
    float* k_out     = out + B * K;
    float* c_out     = out + 2 * B * K;
    float* w_out     = out + 4 * B * K;

    if (tid < M) {
        unsigned long long mine = a[tid];
        int r = 0;
        for (int q = 0; q < M; ++q) r += (a[q] > mine) ? 1 : 0;

        int fi  = (int)(~(unsigned)(mine & 0xffffffffu));
        float sc = __uint_as_float((unsigned)(mine >> 32));
        int kk  = fi % C;
        int rem = fi / C;
        int jj  = rem % W;
        int ii  = rem / W;
        const float* p = yb + (size_t)(ii * W + jj) * CP;
        float whx = 4.0f * (expf(p[C])     - 1.0f);
        float why = 4.0f * (expf(p[C + 1]) - 1.0f);
        float cx  = 4.0f * (float)jj + p[C + 2];
        float cy  = 4.0f * (float)ii + p[C + 3];

        score_out[b * K + r] = sc;
        k_out[b * K + r]     = (float)kk;
        c_out[(b * K + r) * 2 + 0] = cx;
        c_out[(b * K + r) * 2 + 1] = cy;
        w_out[(b * K + r) * 2 + 0] = whx;
        w_out[(b * K + r) * 2 + 1] = why;
    }

    for (int r = M + tid; r < K; r += 512) {     // degenerate pad only
        score_out[b * K + r] = 0.0f;
        k_out[b * K + r]     = 0.0f;
        c_out[(b * K + r) * 2 + 0] = 0.0f;
        c_out[(b * K + r) * 2 + 1] = 0.0f;
        w_out[(b * K + r) * 2 + 0] = 0.0f;
        w_out[(b * K + r) * 2 + 1] = 0.0f;
    }

    __syncthreads();
    if (tid == 0) g_hcnt[b * 32] = 0;
}

extern "C" void kernel_launch(void* const* d_in, const int* in_sizes, int n_in,
                              void* d_out, int out_size) {
    const float* yp = (const float*)d_in[0];
    float* out = (float*)d_out;

    int total = B * 20 * H * 16;                 // 1,638,400 threads
    peaks_kernel<<<total / 256, 256>>>(yp);
    select_kernel<<<B, 512>>>(yp, out);
}

// round 17
// speedup vs baseline: 2.0669x; 1.1782x over previous
#include <cuda_runtime.h>
#include <math.h>

#define B 64
#define H 80
#define W 80
#define C 80
#define CP 84
#define K 100
#define HI_MAX 16384
#define CACHE 1024
#define NBINS 2048       // key>>20; positive float keys < 0x7F800000 -> bin < 2040
#define EQCAP 1024
#define CUTOFF 3.0f      // hi = peaks with score > CUTOFF; exact when n_hi >= K

// pk = (float_bits(score) << 32) | ~sidx : plain u64 '>' == (score desc, idx asc),
// matching jax stable argsort of -score.
__device__ unsigned long long g_hi[B][HI_MAX];
__device__ int g_hcnt[B * 32];

__device__ __forceinline__ bool is_peak(const float* __restrict__ yb,
                                        int i, int j, int c, float val) {
    const size_t rowS = (size_t)W * CP;
    float m = __int_as_float(0xff800000);
    #pragma unroll
    for (int di = -1; di <= 1; ++di) {
        int ni = i + di;
        if (ni < 0 || ni >= H) continue;
        #pragma unroll
        for (int dj = -1; dj <= 1; ++dj) {
            if (di == 0 && dj == 0) continue;
            int nj = j + dj;
            if (nj < 0 || nj >= W) continue;
            m = fmaxf(m, yb[(size_t)ni * rowS + (size_t)nj * CP + c]);
        }
    }
    return val >= m;   // max(window) = max(val, m); val==max <=> val >= m
}

// ---------------------------------------------------------------------------
// K1: threshold-first peaks. One thread = 4 channels x 1 row x 5 columns.
// 5 float4 loads (each value loaded ONCE, no halo). Values > CUTOFF (~0.14%)
// get a 3x3 NMS check via 8 scalar neighbor loads (L1/L2-hot).
// threads = B * 20 * 80 * 16 = 1,638,400; blocks uniform in b (100/batch).
__global__ void __launch_bounds__(256) peaks_kernel(const float* __restrict__ y) {
    __shared__ int s_tot, s_base;
    if (threadIdx.x == 0) s_tot = 0;
    __syncthreads();

    int t  = blockIdx.x * 256 + threadIdx.x;
    int cg = t % 20;                 // fastest: channel group
    int i  = (t / 20) % H;           // row
    int st = (t / (20 * H)) % 16;    // column strip
    int b  = t / (20 * H * 16);
    int c0 = cg * 4;
    int j0 = st * 5;

    const size_t rowS = (size_t)W * CP;
    const float* yb = y + (size_t)b * H * rowS;
    const float* base = yb + (size_t)i * rowS + (size_t)j0 * CP + c0;

    float4 v[5];
    #pragma unroll
    for (int jo = 0; jo < 5; ++jo) v[jo] = *(const float4*)(base + jo * CP);

    // stage 1: cheap threshold scan -> raw candidate list
    float    rawv[8];
    unsigned rawp[8];
    int nr = 0;
    #pragma unroll
    for (int jo = 0; jo < 5; ++jo) {
        float arr[4] = {v[jo].x, v[jo].y, v[jo].z, v[jo].w};
        #pragma unroll
        for (int q = 0; q < 4; ++q) {
            if (arr[q] > CUTOFF) {
                if (nr < 8) {
                    rawv[nr] = arr[q];
                    rawp[nr] = (unsigned)((i * W + j0 + jo) * C + c0 + q);
                }
                nr++;
            }
        }
    }
    if (nr > 8) nr = 8;   // P(>8 of 20 values > 3.0) ~ 0 for N(0,1)

    // stage 2: rare NMS verification (8 neighbor loads per raw candidate)
    unsigned long long cand[8];
    int nc = 0;
    for (int e = 0; e < nr; ++e) {
        float val = rawv[e];
        unsigned sidx = rawp[e];
        int c   = (int)(sidx % C);
        int rem = (int)(sidx / C);
        int jj  = rem % W;
        int ii  = rem / W;
        if (is_peak(yb, ii, jj, c, val))
            cand[nc++] = ((unsigned long long)__float_as_uint(val) << 32)
                       | (unsigned)(~sidx);
    }

    // warp prefix + one global atomic per block
    int lane = threadIdx.x & 31;
    int incl = nc;
    #pragma unroll
    for (int d = 1; d < 32; d <<= 1) {
        int o = __shfl_up_sync(0xffffffffu, incl, d);
        if (lane >= d) incl += o;
    }
    int wtot = __shfl_sync(0xffffffffu, incl, 31);
    int wbase = 0;
    if (lane == 31 && wtot > 0) wbase = atomicAdd(&s_tot, wtot);
    wbase = __shfl_sync(0xffffffffu, wbase, 31);
    __syncthreads();
    if (threadIdx.x == 0) {
        int bt = s_tot;
        s_base = bt ? atomicAdd(&g_hcnt[b * 32], bt) : 0;
    }
    __syncthreads();

    int off = s_base + wbase + incl - nc;
    for (int q = 0; q < nc; ++q)
        if (off + q < HI_MAX) g_hi[b][off + q] = cand[q];
}

// ---------------------------------------------------------------------------
// K2: one block per batch: smem-cached candidate list -> smem histogram ->
// exact K-th threshold bin -> compact (> and ==) -> exact rank -> gather.
// Fast path scans the small hi list (~600). Slow path (n_hi < K; never taken
// for this data, correctness only) recomputes ALL peaks of the batch from y.
__global__ void __launch_bounds__(512) select_kernel(const float* __restrict__ y,
                                                     float* __restrict__ out) {
    __shared__ int hist[NBINS];                  // 8KB
    __shared__ unsigned long long chi[CACHE];    // 8KB candidate cache
    __shared__ unsigned long long se[EQCAP];     // 8KB
    __shared__ unsigned long long a[K];
    __shared__ int csums[512];
    __shared__ int s_tbin, s_cA, s_cE;

    int b   = blockIdx.x;
    int tid = threadIdx.x;                      // 512
    int n_hi = g_hcnt[b * 32]; if (n_hi > HI_MAX) n_hi = HI_MAX;
    bool slow = (n_hi < K);                     // exact fallback
    const unsigned long long* hi = g_hi[b];
    const float* yb = y + (size_t)b * H * W * CP;

    int n_c = n_hi < CACHE ? n_hi : CACHE;

    #pragma unroll
    for (int i = tid; i < NBINS; i += 512) hist[i] = 0;
    if (tid == 0) { s_cA = 0; s_cE = 0; s_tbin = -1; }
    if (!slow)
        for (int p = tid; p < n_c; p += 512) chi[p] = hi[p];
    __syncthreads();

    // pass 1: histogram of key>>20 (pk>>52)
    if (!slow) {
        for (int p = tid; p < n_c; p += 512)
            atomicAdd(&hist[(int)(chi[p] >> 52)], 1);
        for (int p = n_c + tid; p < n_hi; p += 512)
            atomicAdd(&hist[(int)(hi[p] >> 52)], 1);
    } else {
        for (int idx = tid; idx < H * W * C; idx += 512) {
            int c = idx % C, rem = idx / C, j = rem % W, i2 = rem / W;
            float val = yb[(size_t)(i2 * W + j) * CP + c];
            if (val > 0.0f && is_peak(yb, i2, j, c, val))
                atomicAdd(&hist[(int)(__float_as_uint(val) >> 20)], 1);
        }
    }
    __syncthreads();

    {
        int s = 0, base = tid * (NBINS / 512);
        #pragma unroll
        for (int q = 0; q < NBINS / 512; ++q) s += hist[base + q];
        csums[tid] = s;
    }
    __syncthreads();

    // parallel threshold: warp 0, 32 segments of 16 csums
    if (tid < 32) {
        int seg = 0, base = tid * 16;
        #pragma unroll
        for (int q = 0; q < 16; ++q) seg += csums[base + q];
        int x = seg;
        #pragma unroll
        for (int d = 1; d < 32; d <<= 1) {
            int o = __shfl_down_sync(0xffffffffu, x, d);
            if (tid + d < 32) x += o;
        }
        int suf_excl = x - seg;                  // total in segments above mine
        if (suf_excl < K && suf_excl + seg >= K) {
            int acc = suf_excl;
            for (int c = base + 15; c >= base; --c) {
                int h = csums[c];
                if (acc + h >= K) {
                    for (int q = (c + 1) * (NBINS / 512) - 1; q >= c * (NBINS / 512); --q) {
                        int hb2 = hist[q];
                        if (acc + hb2 >= K) { s_tbin = q; break; }
                        acc += hb2;
                    }
                    break;
                }
                acc += h;
            }
        }
    }
    __syncthreads();
    int tb = s_tbin;                             // -1 => total < K: take everything

    // pass 2: compact into above-list (<K) and tie-list
    if (!slow) {
        for (int p = tid; p < n_hi; p += 512) {
            unsigned long long pk = (p < n_c) ? chi[p] : hi[p];
            int bin = (int)(pk >> 52);
            if (bin > tb) {
                int q = atomicAdd(&s_cA, 1);
                if (q < K) a[q] = pk;
            } else if (bin == tb) {
                int q = atomicAdd(&s_cE, 1);
                if (q < EQCAP) se[q] = pk;
            }
        }
    } else {
        for (int idx = tid; idx < H * W * C; idx += 512) {
            int c = idx % C, rem = idx / C, j = rem % W, i2 = rem / W;
            float val = yb[(size_t)(i2 * W + j) * CP + c];
            if (val > 0.0f && is_peak(yb, i2, j, c, val)) {
                unsigned key = __float_as_uint(val);
                unsigned long long pk = ((unsigned long long)key << 32)
                                      | (unsigned)(~(unsigned)idx);
                int bin = (int)(key >> 20);
                if (bin > tb) {
                    int q = atomicAdd(&s_cA, 1);
                    if (q < K) a[q] = pk;
                } else if (bin == tb) {
                    int q = atomicAdd(&s_cE, 1);
                    if (q < EQCAP) se[q] = pk;
                }
            }
        }
    }
    __syncthreads();

    int mA = s_cA; if (mA > K) mA = K;
    int nE = s_cE; if (nE > EQCAP) nE = EQCAP;
    int take = K - mA; if (take > nE) take = nE;

    // ties: top 'take' by (score desc, idx asc) == largest packed
    for (int e = tid; e < nE; e += 512) {
        unsigned long long mine = se[e];
        int r = 0;
        for (int q = 0; q < nE; ++q) r += (se[q] > mine) ? 1 : 0;
        if (r < take) a[mA + r] = mine;
    }
    __syncthreads();

    int M = mA + take;                           // == K normally

    float* score_out = out;
    float* k_out     = out + B * K;
    float* c_out     = out + 2 * B * K;
    float* w_out     = out + 4 * B * K;

    if (tid < M) {
        unsigned long long mine = a[tid];
        int r = 0;
        for (int q = 0; q < M; ++q) r += (a[q] > mine) ? 1 : 0;

        int fi  = (int)(~(unsigned)(mine & 0xffffffffu));
        float sc = __uint_as_float((unsigned)(mine >> 32));
        int kk  = fi % C;
        int rem = fi / C;
        int jj  = rem % W;
        int ii  = rem / W;
        const float* p = yb + (size_t)(ii * W + jj) * CP;
        float whx = 4.0f * (expf(p[C])     - 1.0f);
        float why = 4.0f * (expf(p[C + 1]) - 1.0f);
        float cx  = 4.0f * (float)jj + p[C + 2];
        float cy  = 4.0f * (float)ii + p[C + 3];

        score_out[b * K + r] = sc;
        k_out[b * K + r]     = (float)kk;
        c_out[(b * K + r) * 2 + 0] = cx;
        c_out[(b * K + r) * 2 + 1] = cy;
        w_out[(b * K + r) * 2 + 0] = whx;
        w_out[(b * K + r) * 2 + 1] = why;
    }

    for (int r = M + tid; r < K; r += 512) {     // degenerate pad only
        score_out[b * K + r] = 0.0f;
        k_out[b * K + r]     = 0.0f;
        c_out[(b * K + r) * 2 + 0] = 0.0f;
        c_out[(b * K + r) * 2 + 1] = 0.0f;
        w_out[(b * K + r) * 2 + 0] = 0.0f;
        w_out[(b * K + r) * 2 + 1] = 0.0f;
    }

    __syncthreads();
    if (tid == 0) g_hcnt[b * 32] = 0;
}

extern "C" void kernel_launch(void* const* d_in, const int* in_sizes, int n_in,
                              void* d_out, int out_size) {
    const float* yp = (const float*)d_in[0];
    float* out = (float*)d_out;

    int total = B * 20 * H * 16;                 // 1,638,400 threads
    peaks_kernel<<<total / 256, 256>>>(yp);
    select_kernel<<<B, 512>>>(yp, out);
}